// round 13
// baseline (speedup 1.0000x reference)
#include <cuda_runtime.h>
#include <cuda_fp16.h>
#include <mma.h>
#include <cstdint>

using namespace nvcuda;

// Problem dims (fixed instance)
#define V    2048
#define NB   16
#define DI   32
#define DO   64
#define NH   8
#define NPJ  (V*NB)           // 32768
#define ACT_ROWS (NH*12*12)   // 1152
#define CI   (DI*6)           // 192

// ------------------------- device scratch -------------------------
__device__ __align__(16) __half g_crossh[CI*NPJ];    // fp16 cross [ci][n]      13 MB
__device__ __align__(16) __half g_acth[ACT_ROWS*NPJ];// softmaxed act fp16      75 MB
__device__ __align__(16) __half g_nfmh[144*CI*V];    // [(k,r)][ci][p] fp16    113 MB
__device__ __align__(16) float  g_ka[12*DO*V];       // [r][d][p] fp32           6 MB
__device__ __align__(16) __half g_Mh[ACT_ROWS*CI];   // act weights fp16 (pre-scaled 0.5)
__device__ __align__(16) __half g_Wfh[144*DO*CI];    // feat weights per (k,r) fp16
__device__ __align__(16) __half g_Wch[12*DO*CI];     // center weights per r fp16
__device__ __align__(16) __half g_fmTh[CI*V];        // fm transposed [ci][p] fp16

// ------------------------- constants -------------------------
__constant__ float c_VS[12][3] = {
 {0.f, 0.5257311121f, 0.8506508084f},
 {0.f, 0.5257311121f,-0.8506508084f},
 {0.f,-0.5257311121f, 0.8506508084f},
 {0.f,-0.5257311121f,-0.8506508084f},
 { 0.5257311121f, 0.8506508084f,0.f},
 { 0.5257311121f,-0.8506508084f,0.f},
 {-0.5257311121f, 0.8506508084f,0.f},
 {-0.5257311121f,-0.8506508084f,0.f},
 { 0.8506508084f,0.f, 0.5257311121f},
 { 0.8506508084f,0.f,-0.5257311121f},
 {-0.8506508084f,0.f, 0.5257311121f},
 {-0.8506508084f,0.f,-0.5257311121f}};

__constant__ int c_C2V[6][2] = {{0,1},{6,7},{2,11},{4,9},{5,8},{3,10}};

__constant__ int c_INV[12][6] = {
 {0,1,2,3,4,5},{0,5,4,3,2,1},{4,3,0,5,2,1},{1,2,4,3,5,0},
 {3,5,2,0,4,1},{1,4,3,5,0,2},{4,0,3,1,2,5},{1,0,2,4,3,5},
 {4,1,2,5,0,3},{3,1,4,0,2,5},{2,1,4,5,3,0},{4,5,0,3,1,2}};

__constant__ int c_ROLL[5][6] = {
 {0,1,2,3,4,5},{0,2,3,4,5,1},{0,3,4,5,1,2},{0,4,5,1,2,3},{0,5,1,2,3,4}};

__device__ __forceinline__ float w13(const float* __restrict__ Wp, int k, int m) {
    if (k == 0)  return (m == 0) ? Wp[0] : Wp[1];
    if (k == 1)  return (m == 0) ? Wp[2] : Wp[3];
    if (k == 12) return (m == 0) ? Wp[4] : Wp[5];
    int pp = (k - 2) / 5, s = (k - 2) % 5;
    return Wp[6 + pp * 6 + c_ROLL[s][m]];
}

// ------------------------- K0: weight expansion + fm transpose -------------------------
__global__ void k0_weights(const float* __restrict__ W, const float* __restrict__ Wdir,
                           const float* __restrict__ fm) {
    const int N1 = ACT_ROWS * CI;          // 221184
    const int N2 = 144 * DO * CI;          // 1769472
    const int N3 = 12 * DO * CI;           // 147456
    const int N4 = CI * V;                 // 393216
    const int total = N1 + N2 + N3 + N4;
    for (int idx = blockIdx.x * blockDim.x + threadIdx.x; idx < total;
         idx += gridDim.x * blockDim.x) {
        if (idx < N1) {
            int ci = idx % CI, row = idx / CI;
            int r = row % 12, hk = row / 12, k = hk % 12, h = hk / 12;
            int c = ci / 6, i = ci % 6;
            // fold the 1/sqrt(dph)=0.5 logit scale into the weights
            g_Mh[idx] = __float2half_rn(0.5f * w13(Wdir + (h * DI + c) * 18, k, c_INV[r][i]));
        } else if (idx < N1 + N2) {
            int j = idx - N1;
            int ci = j % CI, dj = j / CI, d = dj % DO, kr = dj / DO;
            int r = kr % 12, k = kr / 12;
            g_Wfh[j] = __float2half_rn(w13(W + (d * DI + ci / 6) * 18, k, c_INV[r][ci % 6]));
        } else if (idx < N1 + N2 + N3) {
            int j = idx - N1 - N2;
            int ci = j % CI, dj = j / CI, d = dj % DO, r = dj / DO;
            g_Wch[j] = __float2half_rn(w13(W + (d * DI + ci / 6) * 18, 12, c_INV[r][ci % 6]));
        } else {
            int j = idx - N1 - N2 - N3;
            int p = j % V, ci = j / V;
            g_fmTh[j] = __float2half_rn(fm[((ci / 6) * V + p) * 6 + (ci % 6)]);
        }
    }
}

// ------------------------- K1: per-vertex cross features -------------------------
__global__ void k1_cross(const int* __restrict__ nbr, const float* __restrict__ verts,
                         const float* __restrict__ fm, const float* __restrict__ Wdim) {
    int p = blockIdx.x;
    int t = threadIdx.x;   // 192 threads
    __shared__ int   s_nbr[NB];
    __shared__ float s_cin[DI + 1][NB][6];
    __shared__ float s_wd[(DI + 1) * DI];
    if (t < NB) s_nbr[t] = nbr[p * NB + t];
    for (int x = t; x < (DI + 1) * DI; x += 192) s_wd[x] = Wdim[x];
    __syncthreads();
    if (t < NB) {
        int q = s_nbr[t];
        float cx = verts[p * 3], cy = verts[p * 3 + 1], cz = verts[p * 3 + 2];
        float dx = verts[q * 3] - cx, dy = verts[q * 3 + 1] - cy, dz = verts[q * 3 + 2] - cz;
        float nrm = fmaxf(sqrtf(dx * dx + dy * dy + dz * dz), 1e-12f);
        dx /= nrm; dy /= nrm; dz /= nrm;
        float de[12];
        #pragma unroll
        for (int v = 0; v < 12; v++)
            de[v] = c_VS[v][0] * dx + c_VS[v][1] * dy + c_VS[v][2] * dz;
        #pragma unroll
        for (int i = 0; i < 6; i++)
            s_cin[DI][t][i] = fmaxf(de[c_C2V[i][0]], de[c_C2V[i][1]]);
    }
    for (int x = t; x < DI * NB * 6; x += 192) {
        int c = x / (NB * 6), rem = x % (NB * 6), j = rem / 6, i = rem % 6;
        s_cin[c][j][i] = fm[(c * V + s_nbr[j]) * 6 + i];
    }
    __syncthreads();
    int o = t / 6, i = t % 6;
    for (int j = 0; j < NB; j++) {
        float a = 0.f;
        #pragma unroll
        for (int c = 0; c <= DI; c++) a += s_wd[c * DI + o] * s_cin[c][j][i];
        g_crossh[(size_t)(o * 6 + i) * NPJ + p * NB + j] = __float2half_rn(a);
    }
}

// ------------------------- K2: act logits GEMM + fused softmax ------------------------
// C(1152 x 32768) = Mh @ crossh. Block tile 128x128, 8 warps (2x4), warp 64x32.
// k-step 48: 4 double-buffered iterations, 24 mma each.
__global__ __launch_bounds__(256) void k2_act() {
    extern __shared__ char dyn[];
    __half* sA = (__half*)dyn;             // [2][128][56]  (28672 B)
    __half* sB = (__half*)(dyn + 28672);   // [2][48][136]  (26112 B)
    float*  sC = (float*)dyn;              // [8][64][36]   (73728 B, reuse after loop)

    int m0 = blockIdx.y * 128, n0 = blockIdx.x * 128;
    int tid = threadIdx.x, lane = tid & 31, wid = tid >> 5;
    int wmL = (wid >> 2) * 64, wnL = (wid & 3) * 32;

    wmma::fragment<wmma::accumulator, 16, 16, 16, float> acc[4][2];
    #pragma unroll
    for (int i = 0; i < 4; i++)
        #pragma unroll
        for (int j = 0; j < 2; j++) wmma::fill_fragment(acc[i][j], 0.0f);

    auto copyAB = [&](int kt, int buf) {
        int k0 = kt * 48;
        #pragma unroll
        for (int q = 0; q < 3; q++) {      // A: 128x48 = 768 uint4
            int v = q * 256 + tid;
            int row = v / 6, c8 = (v % 6) * 8;
            *(float4*)&sA[buf * 7168 + row * 56 + c8] =
                *(const float4*)&g_Mh[(size_t)(m0 + row) * CI + k0 + c8];
        }
        #pragma unroll
        for (int q = 0; q < 3; q++) {      // B: 48x128 = 768 uint4
            int v = q * 256 + tid;
            int row = v >> 4, c8 = (v & 15) * 8;
            *(float4*)&sB[buf * 6528 + row * 136 + c8] =
                *(const float4*)&g_crossh[(size_t)(k0 + row) * NPJ + n0 + c8];
        }
    };

    copyAB(0, 0);
    __syncthreads();
    for (int kt = 0; kt < 4; kt++) {
        int buf = kt & 1;
        if (kt + 1 < 4) copyAB(kt + 1, buf ^ 1);
        #pragma unroll
        for (int kk = 0; kk < 3; kk++) {
            wmma::fragment<wmma::matrix_a, 16, 16, 16, __half, wmma::row_major> af[4];
            wmma::fragment<wmma::matrix_b, 16, 16, 16, __half, wmma::row_major> bf[2];
            #pragma unroll
            for (int i = 0; i < 4; i++)
                wmma::load_matrix_sync(af[i], &sA[buf * 7168 + (wmL + i * 16) * 56 + kk * 16], 56);
            #pragma unroll
            for (int j = 0; j < 2; j++)
                wmma::load_matrix_sync(bf[j], &sB[buf * 6528 + (kk * 16) * 136 + wnL + j * 16], 136);
            #pragma unroll
            for (int i = 0; i < 4; i++)
                #pragma unroll
                for (int j = 0; j < 2; j++)
                    wmma::mma_sync(acc[i][j], af[i], bf[j], acc[i][j]);
        }
        __syncthreads();
    }

    // --- fused softmax epilogue ---
    float* sCw = sC + wid * 64 * 36;       // per-warp 64x36 tile
    #pragma unroll
    for (int i = 0; i < 4; i++)
        #pragma unroll
        for (int j = 0; j < 2; j++)
            wmma::store_matrix_sync(&sCw[(i * 16) * 36 + j * 16], acc[i][j], 36,
                                    wmma::mem_row_major);
    __syncwarp();
    #pragma unroll
    for (int it = 0; it < 4; it++) {
        int g = lane + it * 32;            // 0..127 groups: 64 rows x 2 halves
        int row = g >> 1, half = g & 1;
        const float* src = &sCw[row * 36 + half * 16];
        float v[16];
        #pragma unroll
        for (int q = 0; q < 16; q++) v[q] = src[q];
        float mx = v[0];
        #pragma unroll
        for (int q = 1; q < 16; q++) mx = fmaxf(mx, v[q]);
        float s = 0.f;
        #pragma unroll
        for (int q = 0; q < 16; q++) { v[q] = __expf(v[q] - mx); s += v[q]; }
        float inv = 1.f / s;
        __align__(16) __half hv[16];
        #pragma unroll
        for (int q = 0; q < 16; q++) hv[q] = __float2half_rn(v[q] * inv);
        size_t off = (size_t)(m0 + wmL + row) * NPJ + n0 + wnL + half * 16;
        *(uint4*)&g_acth[off]     = *(uint4*)&hv[0];
        *(uint4*)&g_acth[off + 8] = *(uint4*)&hv[8];
    }
}

// ------------------------- K4a: nfm via per-(p,h) tensor GEMMs ------------------------
// nfm_block[144 rows=(k,r)][24 ci] = act_p[144][16 j] @ cross_p[16 j][24 ci]
// CTA = (16 p's, one head h). cross smem layout [ci][j] is directly a wmma
// col_major B fragment. 9 row-tiles x 2 ci-tiles x 16 p wmma (single k=16 step).
// Output repacked through smem staging so nfm writes are 32B-coalesced.
#define K4A_SMEM 156672
__global__ __launch_bounds__(256) void k4a_nfm() {
    extern __shared__ char dyn4[];
    __half* sAct = (__half*)dyn4;                 // pl*3472 + l*24 + j   (111104 B)
    __half* sCrs = (__half*)(dyn4 + 111104);      // pl*784 + ci*24 + j   ( 25088 B)
    __half* sStg = (__half*)(dyn4 + 136192);      // (l*24 + ci)*16 + pl  ( 12288 B)
    float*  sScr = (float*)(dyn4 + 148480);       // wid*256 + e          (  8192 B)

    int h = blockIdx.y;
    int p0 = blockIdx.x * 16;
    int tid = threadIdx.x, lane = tid & 31, wid = tid >> 5;

    // load act: 144 rows x 16 p x 16 j (4608 uint4)
    #pragma unroll
    for (int q = 0; q < 18; q++) {
        int v = q * 256 + tid;
        int l = v >> 5, rem = v & 31, pl = rem >> 1, hf = rem & 1;
        *(uint4*)&sAct[pl * 3472 + l * 24 + hf * 8] =
            *(const uint4*)&g_acth[(size_t)(h * 144 + l) * NPJ + (p0 + pl) * NB + hf * 8];
    }
    // load cross: 24 rows x 16 p x 16 j (768 uint4)
    #pragma unroll
    for (int q = 0; q < 3; q++) {
        int v = q * 256 + tid;
        int ci = v >> 5, rem = v & 31, pl = rem >> 1, hf = rem & 1;
        *(uint4*)&sCrs[pl * 784 + ci * 24 + hf * 8] =
            *(const uint4*)&g_crossh[(size_t)(h * 24 + ci) * NPJ + (p0 + pl) * NB + hf * 8];
    }
    {   // zero pad rows 24..31 (256 uint4)
        int v = tid;
        int ci = 24 + (v >> 5), rem = v & 31, pl = rem >> 1, hf = rem & 1;
        uint4 z = make_uint4(0, 0, 0, 0);
        *(uint4*)&sCrs[pl * 784 + ci * 24 + hf * 8] = z;
    }
    __syncthreads();

    for (int t = 0; t < 9; t++) {
        #pragma unroll
        for (int pi = 0; pi < 2; pi++) {
            int pl = wid * 2 + pi;
            wmma::fragment<wmma::matrix_a, 16, 16, 16, __half, wmma::row_major> af;
            wmma::load_matrix_sync(af, &sAct[pl * 3472 + t * 16 * 24], 24);
            #pragma unroll
            for (int bt = 0; bt < 2; bt++) {
                wmma::fragment<wmma::matrix_b, 16, 16, 16, __half, wmma::col_major> bf;
                wmma::load_matrix_sync(bf, &sCrs[pl * 784 + bt * 16 * 24], 24);
                wmma::fragment<wmma::accumulator, 16, 16, 16, float> acc;
                wmma::fill_fragment(acc, 0.0f);
                wmma::mma_sync(acc, af, bf, acc);
                wmma::store_matrix_sync(&sScr[wid * 256], acc, 16, wmma::mem_row_major);
                __syncwarp();
                int nci = bt ? 8 : 16;     // ci tile 1 only has 8 valid cols
                #pragma unroll
                for (int q = 0; q < 8; q++) {
                    int e = lane * 8 + q;
                    int row = e >> 4, col = e & 15;
                    if (col < nci)
                        sStg[(row * 24 + bt * 16 + col) * 16 + pl] =
                            __float2half_rn(sScr[wid * 256 + e]);
                }
                __syncwarp();
            }
        }
        __syncthreads();
        // flush staging: 16 rows x 24 ci x 16 p (768 uint4)
        #pragma unroll
        for (int q = 0; q < 3; q++) {
            int v = q * 256 + tid;
            int l = v / 48, rem = v % 48, ci = rem >> 1, hf = rem & 1;
            *(uint4*)&g_nfmh[((size_t)(t * 16 + l) * CI + h * 24 + ci) * V + p0 + hf * 8] =
                *(const uint4*)&sStg[(l * 24 + ci) * 16 + hf * 8];
        }
        __syncthreads();
    }
}

// ------------------------- K4b: ka[r] = sum over 13 slabs of W_slab @ B_slab ----------
// Per r: 12 x (Wf(k,r) 64x192 @ nfm(k,r) 192x2048) + Wc(r) @ fmT. Accum fp32 -> g_ka.
// grid (32, 12) = 384 CTAs, 128 threads = 4 warps; block tile 64 x 64, k-step 32,
// 78 double-buffered iterations, 8 MMAs/iter.
__global__ __launch_bounds__(128) void k4b_ka() {
    __shared__ __align__(16) __half sA[2][64][40];   // 64 x 32 (+8 pad)
    __shared__ __align__(16) __half sB[2][32][72];   // 32 x 64 (+8 pad)
    int r = blockIdx.y;
    int n0 = blockIdx.x * 64;
    int tid = threadIdx.x, wid = tid >> 5;
    int wn = wid * 16;

    wmma::fragment<wmma::accumulator, 16, 16, 16, float> acc[4];
    #pragma unroll
    for (int i = 0; i < 4; i++) wmma::fill_fragment(acc[i], 0.0f);

    auto aPtr = [&](int s) -> const __half* {
        return (s < 12) ? g_Wfh + (size_t)(s * 12 + r) * DO * CI
                        : g_Wch + (size_t)r * DO * CI;
    };
    auto bPtr = [&](int s) -> const __half* {
        return (s < 12) ? g_nfmh + (size_t)(s * 12 + r) * CI * V
                        : g_fmTh;
    };

    auto copyAB = [&](int it, int buf) {
        int s = it / 6, k0 = (it % 6) * 32;
        const __half* A = aPtr(s);
        const __half* B = bPtr(s);
        #pragma unroll
        for (int q = 0; q < 2; q++) {      // A: 64x32 = 256 float4, 2/thread
            int f = tid * 2 + q;
            int row = f >> 2, seg = (f & 3) * 8;
            *(float4*)&sA[buf][row][seg] = *(const float4*)&A[(size_t)row * CI + k0 + seg];
        }
        #pragma unroll
        for (int q = 0; q < 2; q++) {      // B: 32x64 = 256 float4, 2/thread
            int f = tid * 2 + q;
            int row = f >> 3, seg = (f & 7) * 8;
            *(float4*)&sB[buf][row][seg] = *(const float4*)&B[(size_t)(k0 + row) * V + n0 + seg];
        }
    };

    const int NIT = 13 * 6;    // 78
    copyAB(0, 0);
    __syncthreads();
    for (int it = 0; it < NIT; it++) {
        int buf = it & 1;
        if (it + 1 < NIT) copyAB(it + 1, buf ^ 1);
        #pragma unroll
        for (int kk = 0; kk < 2; kk++) {
            wmma::fragment<wmma::matrix_a, 16, 16, 16, __half, wmma::row_major> af[4];
            wmma::fragment<wmma::matrix_b, 16, 16, 16, __half, wmma::row_major> bf;
            #pragma unroll
            for (int i = 0; i < 4; i++)
                wmma::load_matrix_sync(af[i], &sA[buf][i * 16][kk * 16], 40);
            wmma::load_matrix_sync(bf, &sB[buf][kk * 16][wn], 72);
            #pragma unroll
            for (int i = 0; i < 4; i++)
                wmma::mma_sync(acc[i], af[i], bf, acc[i]);
        }
        __syncthreads();
    }
    #pragma unroll
    for (int i = 0; i < 4; i++)
        wmma::store_matrix_sync(g_ka + ((size_t)r * DO + i * 16) * V + n0 + wn,
                                acc[i], V, wmma::mem_row_major);
}

// ------------------------- K5: color-pair max + fm copy ----------------
__global__ void k5_final(const float* __restrict__ fm, float* __restrict__ out) {
    int idx = blockIdx.x * blockDim.x + threadIdx.x;
    const int NKA = DO * V;                // 131072
    if (idx < NKA) {
        int d = idx / V, p = idx % V;
        float ka[12];
        #pragma unroll
        for (int r = 0; r < 12; r++) ka[r] = g_ka[(size_t)(r * DO + d) * V + p];
        #pragma unroll
        for (int cc = 0; cc < 6; cc++)
            out[d * (V * 6) + p * 6 + cc] = fmaxf(ka[c_C2V[cc][0]], ka[c_C2V[cc][1]]);
    } else {
        int j = idx - NKA;
        if (j < DI * V * 6)
            out[DO * V * 6 + j] = fm[j];
    }
}

// ------------------------- launch -------------------------
extern "C" void kernel_launch(void* const* d_in, const int* in_sizes, int n_in,
                              void* d_out, int out_size) {
    const int*   nbr   = (const int*)d_in[0];
    const float* verts = (const float*)d_in[1];
    const float* fm    = (const float*)d_in[2];
    const float* Wdim  = (const float*)d_in[3];
    const float* W     = (const float*)d_in[4];
    const float* Wdir  = (const float*)d_in[5];
    float* out = (float*)d_out;

    const int K2_SMEM = 8 * 64 * 36 * 4;   // 73728 B (sC; covers sA+sB too)
    cudaFuncSetAttribute(k2_act, cudaFuncAttributeMaxDynamicSharedMemorySize, K2_SMEM);
    cudaFuncSetAttribute(k4a_nfm, cudaFuncAttributeMaxDynamicSharedMemorySize, K4A_SMEM);

    k0_weights<<<512, 256>>>(W, Wdir, fm);
    k1_cross<<<V, 192>>>(nbr, verts, fm, Wdim);
    k2_act<<<dim3(NPJ / 128, ACT_ROWS / 128), 256, K2_SMEM>>>();
    k4a_nfm<<<dim3(V / 16, 8), 256, K4A_SMEM>>>();
    k4b_ka<<<dim3(V / 64, 12), 128>>>();
    k5_final<<<(DO * V + DI * V * 6 + 255) / 256, 256>>>(fm, out);
}

// round 14
// speedup vs baseline: 2.5748x; 2.5748x over previous
#include <cuda_runtime.h>
#include <cuda_fp16.h>
#include <mma.h>
#include <cstdint>

using namespace nvcuda;

// Problem dims (fixed instance)
#define V    2048
#define NB   16
#define DI   32
#define DO   64
#define NH   8
#define NPJ  (V*NB)           // 32768
#define ACT_ROWS (NH*12*12)   // 1152
#define CI   (DI*6)           // 192

// ------------------------- device scratch -------------------------
__device__ __align__(16) __half g_crossh[CI*NPJ];    // fp16 cross [ci][n]      13 MB
__device__ __align__(16) __half g_acth[ACT_ROWS*NPJ];// softmaxed act fp16      75 MB
__device__ __align__(16) __half g_nfmh[144*CI*V];    // [(k,r)][ci][p] fp16    113 MB
__device__ __align__(16) float  g_ka[12*DO*V];       // [r][d][p] fp32           6 MB
__device__ __align__(16) __half g_Mh[ACT_ROWS*CI];   // act weights fp16 (pre-scaled 0.5)
__device__ __align__(16) __half g_Wfh[144*DO*CI];    // feat weights per (k,r) fp16
__device__ __align__(16) __half g_Wch[12*DO*CI];     // center weights per r fp16
__device__ __align__(16) __half g_fmTh[CI*V];        // fm transposed [ci][p] fp16

// ------------------------- constants -------------------------
__constant__ float c_VS[12][3] = {
 {0.f, 0.5257311121f, 0.8506508084f},
 {0.f, 0.5257311121f,-0.8506508084f},
 {0.f,-0.5257311121f, 0.8506508084f},
 {0.f,-0.5257311121f,-0.8506508084f},
 { 0.5257311121f, 0.8506508084f,0.f},
 { 0.5257311121f,-0.8506508084f,0.f},
 {-0.5257311121f, 0.8506508084f,0.f},
 {-0.5257311121f,-0.8506508084f,0.f},
 { 0.8506508084f,0.f, 0.5257311121f},
 { 0.8506508084f,0.f,-0.5257311121f},
 {-0.8506508084f,0.f, 0.5257311121f},
 {-0.8506508084f,0.f,-0.5257311121f}};

__constant__ int c_C2V[6][2] = {{0,1},{6,7},{2,11},{4,9},{5,8},{3,10}};

__constant__ int c_INV[12][6] = {
 {0,1,2,3,4,5},{0,5,4,3,2,1},{4,3,0,5,2,1},{1,2,4,3,5,0},
 {3,5,2,0,4,1},{1,4,3,5,0,2},{4,0,3,1,2,5},{1,0,2,4,3,5},
 {4,1,2,5,0,3},{3,1,4,0,2,5},{2,1,4,5,3,0},{4,5,0,3,1,2}};

__constant__ int c_ROLL[5][6] = {
 {0,1,2,3,4,5},{0,2,3,4,5,1},{0,3,4,5,1,2},{0,4,5,1,2,3},{0,5,1,2,3,4}};

__device__ __forceinline__ float w13(const float* __restrict__ Wp, int k, int m) {
    if (k == 0)  return (m == 0) ? Wp[0] : Wp[1];
    if (k == 1)  return (m == 0) ? Wp[2] : Wp[3];
    if (k == 12) return (m == 0) ? Wp[4] : Wp[5];
    int pp = (k - 2) / 5, s = (k - 2) % 5;
    return Wp[6 + pp * 6 + c_ROLL[s][m]];
}

// ------------------------- K0: weight expansion + fm transpose -------------------------
__global__ void k0_weights(const float* __restrict__ W, const float* __restrict__ Wdir,
                           const float* __restrict__ fm) {
    const int N1 = ACT_ROWS * CI;          // 221184
    const int N2 = 144 * DO * CI;          // 1769472
    const int N3 = 12 * DO * CI;           // 147456
    const int N4 = CI * V;                 // 393216
    const int total = N1 + N2 + N3 + N4;
    for (int idx = blockIdx.x * blockDim.x + threadIdx.x; idx < total;
         idx += gridDim.x * blockDim.x) {
        if (idx < N1) {
            int ci = idx % CI, row = idx / CI;
            int r = row % 12, hk = row / 12, k = hk % 12, h = hk / 12;
            int c = ci / 6, i = ci % 6;
            // fold the 1/sqrt(dph)=0.5 logit scale into the weights
            g_Mh[idx] = __float2half_rn(0.5f * w13(Wdir + (h * DI + c) * 18, k, c_INV[r][i]));
        } else if (idx < N1 + N2) {
            int j = idx - N1;
            int ci = j % CI, dj = j / CI, d = dj % DO, kr = dj / DO;
            int r = kr % 12, k = kr / 12;
            g_Wfh[j] = __float2half_rn(w13(W + (d * DI + ci / 6) * 18, k, c_INV[r][ci % 6]));
        } else if (idx < N1 + N2 + N3) {
            int j = idx - N1 - N2;
            int ci = j % CI, dj = j / CI, d = dj % DO, r = dj / DO;
            g_Wch[j] = __float2half_rn(w13(W + (d * DI + ci / 6) * 18, 12, c_INV[r][ci % 6]));
        } else {
            int j = idx - N1 - N2 - N3;
            int p = j % V, ci = j / V;
            g_fmTh[j] = __float2half_rn(fm[((ci / 6) * V + p) * 6 + (ci % 6)]);
        }
    }
}

// ------------------------- K1: per-vertex cross features -------------------------
__global__ void k1_cross(const int* __restrict__ nbr, const float* __restrict__ verts,
                         const float* __restrict__ fm, const float* __restrict__ Wdim) {
    int p = blockIdx.x;
    int t = threadIdx.x;   // 192 threads
    __shared__ int   s_nbr[NB];
    __shared__ float s_cin[DI + 1][NB][6];
    __shared__ float s_wd[(DI + 1) * DI];
    if (t < NB) s_nbr[t] = nbr[p * NB + t];
    for (int x = t; x < (DI + 1) * DI; x += 192) s_wd[x] = Wdim[x];
    __syncthreads();
    if (t < NB) {
        int q = s_nbr[t];
        float cx = verts[p * 3], cy = verts[p * 3 + 1], cz = verts[p * 3 + 2];
        float dx = verts[q * 3] - cx, dy = verts[q * 3 + 1] - cy, dz = verts[q * 3 + 2] - cz;
        float nrm = fmaxf(sqrtf(dx * dx + dy * dy + dz * dz), 1e-12f);
        dx /= nrm; dy /= nrm; dz /= nrm;
        float de[12];
        #pragma unroll
        for (int v = 0; v < 12; v++)
            de[v] = c_VS[v][0] * dx + c_VS[v][1] * dy + c_VS[v][2] * dz;
        #pragma unroll
        for (int i = 0; i < 6; i++)
            s_cin[DI][t][i] = fmaxf(de[c_C2V[i][0]], de[c_C2V[i][1]]);
    }
    for (int x = t; x < DI * NB * 6; x += 192) {
        int c = x / (NB * 6), rem = x % (NB * 6), j = rem / 6, i = rem % 6;
        s_cin[c][j][i] = fm[(c * V + s_nbr[j]) * 6 + i];
    }
    __syncthreads();
    int o = t / 6, i = t % 6;
    for (int j = 0; j < NB; j++) {
        float a = 0.f;
        #pragma unroll
        for (int c = 0; c <= DI; c++) a += s_wd[c * DI + o] * s_cin[c][j][i];
        g_crossh[(size_t)(o * 6 + i) * NPJ + p * NB + j] = __float2half_rn(a);
    }
}

// ------------------------- K2: act logits GEMM + fused softmax ------------------------
// C(1152 x 32768) = Mh @ crossh. Block tile 128x128, 8 warps (2x4), warp 64x32.
// Smem-staged, double-buffered plain LDG->STS, k-step 16 (proven R11 config).
__global__ __launch_bounds__(256) void k2_act() {
    extern __shared__ char dyn[];
    __half* sA = (__half*)dyn;             // [2][128][24]  (12288 B)
    __half* sB = (__half*)(dyn + 12288);   // [2][16][136]  ( 8704 B)
    float*  sC = (float*)dyn;              // [8][64][36]   (73728 B, reuse after loop)

    int m0 = blockIdx.y * 128, n0 = blockIdx.x * 128;
    int tid = threadIdx.x, lane = tid & 31, wid = tid >> 5;
    int wmL = (wid >> 2) * 64, wnL = (wid & 3) * 32;

    wmma::fragment<wmma::accumulator, 16, 16, 16, float> acc[4][2];
    #pragma unroll
    for (int i = 0; i < 4; i++)
        #pragma unroll
        for (int j = 0; j < 2; j++) wmma::fill_fragment(acc[i][j], 0.0f);

    int ar = tid >> 1, ac = (tid & 1) * 8;
    int br = tid >> 4, bc = (tid & 15) * 8;

    auto copyAB = [&](int kt, int buf) {
        int k0 = kt * 16;
        *(float4*)&sA[buf * 3072 + ar * 24 + ac] =
            *(const float4*)&g_Mh[(size_t)(m0 + ar) * CI + k0 + ac];
        *(float4*)&sB[buf * 2176 + br * 136 + bc] =
            *(const float4*)&g_crossh[(size_t)(k0 + br) * NPJ + n0 + bc];
    };

    copyAB(0, 0);
    __syncthreads();
    for (int kt = 0; kt < 12; kt++) {
        int buf = kt & 1;
        if (kt + 1 < 12) copyAB(kt + 1, buf ^ 1);
        wmma::fragment<wmma::matrix_a, 16, 16, 16, __half, wmma::row_major> af[4];
        wmma::fragment<wmma::matrix_b, 16, 16, 16, __half, wmma::row_major> bf[2];
        #pragma unroll
        for (int i = 0; i < 4; i++)
            wmma::load_matrix_sync(af[i], &sA[buf * 3072 + (wmL + i * 16) * 24], 24);
        #pragma unroll
        for (int j = 0; j < 2; j++)
            wmma::load_matrix_sync(bf[j], &sB[buf * 2176 + wnL + j * 16], 136);
        #pragma unroll
        for (int i = 0; i < 4; i++)
            #pragma unroll
            for (int j = 0; j < 2; j++)
                wmma::mma_sync(acc[i][j], af[i], bf[j], acc[i][j]);
        __syncthreads();
    }

    // --- fused softmax epilogue ---
    float* sCw = sC + wid * 64 * 36;       // per-warp 64x36 tile
    #pragma unroll
    for (int i = 0; i < 4; i++)
        #pragma unroll
        for (int j = 0; j < 2; j++)
            wmma::store_matrix_sync(&sCw[(i * 16) * 36 + j * 16], acc[i][j], 36,
                                    wmma::mem_row_major);
    __syncwarp();
    #pragma unroll
    for (int it = 0; it < 4; it++) {
        int g = lane + it * 32;            // 0..127 groups: 64 rows x 2 halves
        int row = g >> 1, half = g & 1;
        const float* src = &sCw[row * 36 + half * 16];
        float v[16];
        #pragma unroll
        for (int q = 0; q < 16; q++) v[q] = src[q];
        float mx = v[0];
        #pragma unroll
        for (int q = 1; q < 16; q++) mx = fmaxf(mx, v[q]);
        float s = 0.f;
        #pragma unroll
        for (int q = 0; q < 16; q++) { v[q] = __expf(v[q] - mx); s += v[q]; }
        float inv = 1.f / s;
        __align__(16) __half hv[16];
        #pragma unroll
        for (int q = 0; q < 16; q++) hv[q] = __float2half_rn(v[q] * inv);
        size_t off = (size_t)(m0 + wmL + row) * NPJ + n0 + wnL + half * 16;
        *(uint4*)&g_acth[off]     = *(uint4*)&hv[0];
        *(uint4*)&g_acth[off + 8] = *(uint4*)&hv[8];
    }
}

// ------------------------- K4a: nfm[(k,r)][ci][p] (fp16) = sum_j act*cross ------------
// One thread per p. grid (V/128, 12, 8) keyed on (p-tile, k, h). The 12 act rows
// for (h,k) are register-cached in THREE passes of 4 rows (fp32, ~64 cache regs)
// to raise occupancy vs the 2x6 variant (regs 145 -> ~110). Cross re-read 3x
// (L2-resident, cheap). Same serial 16-FMA dot per output -> identical numerics.
__global__ __launch_bounds__(128) void k4a_nfm() {
    int k = blockIdx.y;                    // 0..11
    int h = blockIdx.z;                    // 0..7
    int p = blockIdx.x * 128 + threadIdx.x;
    int abase = (h * 12 + k) * 12;
    #pragma unroll
    for (int rp = 0; rp < 3; rp++) {
        float av[4][16];
        #pragma unroll
        for (int rr = 0; rr < 4; rr++) {
            size_t aoff = (size_t)(abase + rp * 4 + rr) * NPJ + p * NB;
            uint4 a0 = *(const uint4*)&g_acth[aoff];
            uint4 a1 = *(const uint4*)&g_acth[aoff + 8];
            const __half2* h0 = (const __half2*)&a0;
            const __half2* h1 = (const __half2*)&a1;
            #pragma unroll
            for (int q = 0; q < 4; q++) {
                float2 f0 = __half22float2(h0[q]);
                float2 f1 = __half22float2(h1[q]);
                av[rr][q * 2] = f0.x;     av[rr][q * 2 + 1] = f0.y;
                av[rr][8 + q * 2] = f1.x; av[rr][8 + q * 2 + 1] = f1.y;
            }
        }
        #pragma unroll 2
        for (int cc = 0; cc < 24; cc++) {
            int ci = h * 24 + cc;
            size_t xoff = (size_t)ci * NPJ + p * NB;
            uint4 x0 = *(const uint4*)&g_crossh[xoff];
            uint4 x1 = *(const uint4*)&g_crossh[xoff + 8];
            const __half2* h0 = (const __half2*)&x0;
            const __half2* h1 = (const __half2*)&x1;
            float xv[16];
            #pragma unroll
            for (int q = 0; q < 4; q++) {
                float2 f0 = __half22float2(h0[q]);
                float2 f1 = __half22float2(h1[q]);
                xv[q * 2] = f0.x;     xv[q * 2 + 1] = f0.y;
                xv[8 + q * 2] = f1.x; xv[8 + q * 2 + 1] = f1.y;
            }
            #pragma unroll
            for (int rr = 0; rr < 4; rr++) {
                float acc = 0.f;
                #pragma unroll
                for (int q = 0; q < 16; q++) acc += av[rr][q] * xv[q];
                g_nfmh[((size_t)(k * 12 + rp * 4 + rr) * CI + ci) * V + p] =
                    __float2half_rn(acc);
            }
        }
    }
}

// ------------------------- K4b: ka[r] = sum over 13 slabs of W_slab @ B_slab ----------
// Per r: 12 x (Wf(k,r) 64x192 @ nfm(k,r) 192x2048) + Wc(r) @ fmT. Accum fp32 -> g_ka.
// grid (32, 12) = 384 CTAs, 128 threads = 4 warps; block tile 64 x 64, k-step 32,
// 78 double-buffered iterations, 8 MMAs/iter.
__global__ __launch_bounds__(128) void k4b_ka() {
    __shared__ __align__(16) __half sA[2][64][40];   // 64 x 32 (+8 pad)
    __shared__ __align__(16) __half sB[2][32][72];   // 32 x 64 (+8 pad)
    int r = blockIdx.y;
    int n0 = blockIdx.x * 64;
    int tid = threadIdx.x, wid = tid >> 5;
    int wn = wid * 16;

    wmma::fragment<wmma::accumulator, 16, 16, 16, float> acc[4];
    #pragma unroll
    for (int i = 0; i < 4; i++) wmma::fill_fragment(acc[i], 0.0f);

    auto aPtr = [&](int s) -> const __half* {
        return (s < 12) ? g_Wfh + (size_t)(s * 12 + r) * DO * CI
                        : g_Wch + (size_t)r * DO * CI;
    };
    auto bPtr = [&](int s) -> const __half* {
        return (s < 12) ? g_nfmh + (size_t)(s * 12 + r) * CI * V
                        : g_fmTh;
    };

    auto copyAB = [&](int it, int buf) {
        int s = it / 6, k0 = (it % 6) * 32;
        const __half* A = aPtr(s);
        const __half* B = bPtr(s);
        #pragma unroll
        for (int q = 0; q < 2; q++) {      // A: 64x32 = 256 float4, 2/thread
            int f = tid * 2 + q;
            int row = f >> 2, seg = (f & 3) * 8;
            *(float4*)&sA[buf][row][seg] = *(const float4*)&A[(size_t)row * CI + k0 + seg];
        }
        #pragma unroll
        for (int q = 0; q < 2; q++) {      // B: 32x64 = 256 float4, 2/thread
            int f = tid * 2 + q;
            int row = f >> 3, seg = (f & 7) * 8;
            *(float4*)&sB[buf][row][seg] = *(const float4*)&B[(size_t)(k0 + row) * V + n0 + seg];
        }
    };

    const int NIT = 13 * 6;    // 78
    copyAB(0, 0);
    __syncthreads();
    for (int it = 0; it < NIT; it++) {
        int buf = it & 1;
        if (it + 1 < NIT) copyAB(it + 1, buf ^ 1);
        #pragma unroll
        for (int kk = 0; kk < 2; kk++) {
            wmma::fragment<wmma::matrix_a, 16, 16, 16, __half, wmma::row_major> af[4];
            wmma::fragment<wmma::matrix_b, 16, 16, 16, __half, wmma::row_major> bf;
            #pragma unroll
            for (int i = 0; i < 4; i++)
                wmma::load_matrix_sync(af[i], &sA[buf][i * 16][kk * 16], 40);
            wmma::load_matrix_sync(bf, &sB[buf][kk * 16][wn], 72);
            #pragma unroll
            for (int i = 0; i < 4; i++)
                wmma::mma_sync(acc[i], af[i], bf, acc[i]);
        }
        __syncthreads();
    }
    #pragma unroll
    for (int i = 0; i < 4; i++)
        wmma::store_matrix_sync(g_ka + ((size_t)r * DO + i * 16) * V + n0 + wn,
                                acc[i], V, wmma::mem_row_major);
}

// ------------------------- K5: color-pair max + fm copy ----------------
__global__ void k5_final(const float* __restrict__ fm, float* __restrict__ out) {
    int idx = blockIdx.x * blockDim.x + threadIdx.x;
    const int NKA = DO * V;                // 131072
    if (idx < NKA) {
        int d = idx / V, p = idx % V;
        float ka[12];
        #pragma unroll
        for (int r = 0; r < 12; r++) ka[r] = g_ka[(size_t)(r * DO + d) * V + p];
        #pragma unroll
        for (int cc = 0; cc < 6; cc++)
            out[d * (V * 6) + p * 6 + cc] = fmaxf(ka[c_C2V[cc][0]], ka[c_C2V[cc][1]]);
    } else {
        int j = idx - NKA;
        if (j < DI * V * 6)
            out[DO * V * 6 + j] = fm[j];
    }
}

// ------------------------- launch -------------------------
extern "C" void kernel_launch(void* const* d_in, const int* in_sizes, int n_in,
                              void* d_out, int out_size) {
    const int*   nbr   = (const int*)d_in[0];
    const float* verts = (const float*)d_in[1];
    const float* fm    = (const float*)d_in[2];
    const float* Wdim  = (const float*)d_in[3];
    const float* W     = (const float*)d_in[4];
    const float* Wdir  = (const float*)d_in[5];
    float* out = (float*)d_out;

    const int K2_SMEM = 8 * 64 * 36 * 4;   // 73728 B (sC; covers sA+sB too)
    cudaFuncSetAttribute(k2_act, cudaFuncAttributeMaxDynamicSharedMemorySize, K2_SMEM);

    k0_weights<<<512, 256>>>(W, Wdir, fm);
    k1_cross<<<V, 192>>>(nbr, verts, fm, Wdim);
    k2_act<<<dim3(NPJ / 128, ACT_ROWS / 128), 256, K2_SMEM>>>();
    k4a_nfm<<<dim3(V / 128, 12, 8), 128>>>();
    k4b_ka<<<dim3(V / 64, 12), 128>>>();
    k5_final<<<(DO * V + DI * V * 6 + 255) / 256, 256>>>(fm, out);
}

// round 17
// speedup vs baseline: 2.6035x; 1.0112x over previous
#include <cuda_runtime.h>
#include <cuda_fp16.h>
#include <mma.h>
#include <cstdint>

using namespace nvcuda;

// Problem dims (fixed instance)
#define V    2048
#define NB   16
#define DI   32
#define DO   64
#define NH   8
#define NPJ  (V*NB)           // 32768
#define ACT_ROWS (NH*12*12)   // 1152
#define CI   (DI*6)           // 192

// ------------------------- device scratch -------------------------
__device__ __align__(16) __half g_crossh[CI*NPJ];    // fp16 cross [ci][n]      13 MB
__device__ __align__(16) __half g_acth[ACT_ROWS*NPJ];// softmaxed act fp16      75 MB
__device__ __align__(16) __half g_nfmh[144*CI*V];    // [(k,r)][ci][p] fp16    113 MB
__device__ __align__(16) float  g_ka[12*DO*V];       // [r][d][p] fp32           6 MB
__device__ __align__(16) __half g_Mh[ACT_ROWS*CI];   // act weights fp16 (pre-scaled 0.5)
__device__ __align__(16) __half g_Wfh[144*DO*CI];    // feat weights per (k,r) fp16
__device__ __align__(16) __half g_Wch[12*DO*CI];     // center weights per r fp16
__device__ __align__(16) __half g_fmTh[CI*V];        // fm transposed [ci][p] fp16

// ------------------------- constants -------------------------
__constant__ float c_VS[12][3] = {
 {0.f, 0.5257311121f, 0.8506508084f},
 {0.f, 0.5257311121f,-0.8506508084f},
 {0.f,-0.5257311121f, 0.8506508084f},
 {0.f,-0.5257311121f,-0.8506508084f},
 { 0.5257311121f, 0.8506508084f,0.f},
 { 0.5257311121f,-0.8506508084f,0.f},
 {-0.5257311121f, 0.8506508084f,0.f},
 {-0.5257311121f,-0.8506508084f,0.f},
 { 0.8506508084f,0.f, 0.5257311121f},
 { 0.8506508084f,0.f,-0.5257311121f},
 {-0.8506508084f,0.f, 0.5257311121f},
 {-0.8506508084f,0.f,-0.5257311121f}};

__constant__ int c_C2V[6][2] = {{0,1},{6,7},{2,11},{4,9},{5,8},{3,10}};

__constant__ int c_INV[12][6] = {
 {0,1,2,3,4,5},{0,5,4,3,2,1},{4,3,0,5,2,1},{1,2,4,3,5,0},
 {3,5,2,0,4,1},{1,4,3,5,0,2},{4,0,3,1,2,5},{1,0,2,4,3,5},
 {4,1,2,5,0,3},{3,1,4,0,2,5},{2,1,4,5,3,0},{4,5,0,3,1,2}};

__constant__ int c_ROLL[5][6] = {
 {0,1,2,3,4,5},{0,2,3,4,5,1},{0,3,4,5,1,2},{0,4,5,1,2,3},{0,5,1,2,3,4}};

__device__ __forceinline__ float w13(const float* __restrict__ Wp, int k, int m) {
    if (k == 0)  return (m == 0) ? Wp[0] : Wp[1];
    if (k == 1)  return (m == 0) ? Wp[2] : Wp[3];
    if (k == 12) return (m == 0) ? Wp[4] : Wp[5];
    int pp = (k - 2) / 5, s = (k - 2) % 5;
    return Wp[6 + pp * 6 + c_ROLL[s][m]];
}

// ------------------------- packed f32x2 helpers (sm_103a) -------------------------
__device__ __forceinline__ unsigned long long h2_to_f32x2(__half2 h) {
    float2 f = __half22float2(h);
    unsigned long long r;
    asm("mov.b64 %0, {%1, %2};" : "=l"(r) : "f"(f.x), "f"(f.y));
    return r;
}
__device__ __forceinline__ unsigned long long ffma2(unsigned long long a,
                                                    unsigned long long b,
                                                    unsigned long long c) {
    unsigned long long d;
    asm("fma.rn.f32x2 %0, %1, %2, %3;" : "=l"(d) : "l"(a), "l"(b), "l"(c));
    return d;
}

// ------------------------- K0: weight expansion + fm transpose -------------------------
__global__ void k0_weights(const float* __restrict__ W, const float* __restrict__ Wdir,
                           const float* __restrict__ fm) {
    const int N1 = ACT_ROWS * CI;          // 221184
    const int N2 = 144 * DO * CI;          // 1769472
    const int N3 = 12 * DO * CI;           // 147456
    const int N4 = CI * V;                 // 393216
    const int total = N1 + N2 + N3 + N4;
    for (int idx = blockIdx.x * blockDim.x + threadIdx.x; idx < total;
         idx += gridDim.x * blockDim.x) {
        if (idx < N1) {
            int ci = idx % CI, row = idx / CI;
            int r = row % 12, hk = row / 12, k = hk % 12, h = hk / 12;
            int c = ci / 6, i = ci % 6;
            // fold the 1/sqrt(dph)=0.5 logit scale into the weights
            g_Mh[idx] = __float2half_rn(0.5f * w13(Wdir + (h * DI + c) * 18, k, c_INV[r][i]));
        } else if (idx < N1 + N2) {
            int j = idx - N1;
            int ci = j % CI, dj = j / CI, d = dj % DO, kr = dj / DO;
            int r = kr % 12, k = kr / 12;
            g_Wfh[j] = __float2half_rn(w13(W + (d * DI + ci / 6) * 18, k, c_INV[r][ci % 6]));
        } else if (idx < N1 + N2 + N3) {
            int j = idx - N1 - N2;
            int ci = j % CI, dj = j / CI, d = dj % DO, r = dj / DO;
            g_Wch[j] = __float2half_rn(w13(W + (d * DI + ci / 6) * 18, 12, c_INV[r][ci % 6]));
        } else {
            int j = idx - N1 - N2 - N3;
            int p = j % V, ci = j / V;
            g_fmTh[j] = __float2half_rn(fm[((ci / 6) * V + p) * 6 + (ci % 6)]);
        }
    }
}

// ------------------------- K1: per-vertex cross features -------------------------
__global__ void k1_cross(const int* __restrict__ nbr, const float* __restrict__ verts,
                         const float* __restrict__ fm, const float* __restrict__ Wdim) {
    int p = blockIdx.x;
    int t = threadIdx.x;   // 192 threads
    __shared__ int   s_nbr[NB];
    __shared__ float s_cin[DI + 1][NB][6];
    __shared__ float s_wd[(DI + 1) * DI];
    if (t < NB) s_nbr[t] = nbr[p * NB + t];
    for (int x = t; x < (DI + 1) * DI; x += 192) s_wd[x] = Wdim[x];
    __syncthreads();
    if (t < NB) {
        int q = s_nbr[t];
        float cx = verts[p * 3], cy = verts[p * 3 + 1], cz = verts[p * 3 + 2];
        float dx = verts[q * 3] - cx, dy = verts[q * 3 + 1] - cy, dz = verts[q * 3 + 2] - cz;
        float nrm = fmaxf(sqrtf(dx * dx + dy * dy + dz * dz), 1e-12f);
        dx /= nrm; dy /= nrm; dz /= nrm;
        float de[12];
        #pragma unroll
        for (int v = 0; v < 12; v++)
            de[v] = c_VS[v][0] * dx + c_VS[v][1] * dy + c_VS[v][2] * dz;
        #pragma unroll
        for (int i = 0; i < 6; i++)
            s_cin[DI][t][i] = fmaxf(de[c_C2V[i][0]], de[c_C2V[i][1]]);
    }
    for (int x = t; x < DI * NB * 6; x += 192) {
        int c = x / (NB * 6), rem = x % (NB * 6), j = rem / 6, i = rem % 6;
        s_cin[c][j][i] = fm[(c * V + s_nbr[j]) * 6 + i];
    }
    __syncthreads();
    int o = t / 6, i = t % 6;
    for (int j = 0; j < NB; j++) {
        float a = 0.f;
        #pragma unroll
        for (int c = 0; c <= DI; c++) a += s_wd[c * DI + o] * s_cin[c][j][i];
        g_crossh[(size_t)(o * 6 + i) * NPJ + p * NB + j] = __float2half_rn(a);
    }
}

// ------------------------- K2: act logits GEMM + fused softmax ------------------------
// C(1152 x 32768) = Mh @ crossh. Block tile 128x128, 8 warps (2x4), warp 64x32.
// Smem-staged, double-buffered plain LDG->STS, k-step 16 (proven R11 config).
__global__ __launch_bounds__(256) void k2_act() {
    extern __shared__ char dyn[];
    __half* sA = (__half*)dyn;             // [2][128][24]  (12288 B)
    __half* sB = (__half*)(dyn + 12288);   // [2][16][136]  ( 8704 B)
    float*  sC = (float*)dyn;              // [8][64][36]   (73728 B, reuse after loop)

    int m0 = blockIdx.y * 128, n0 = blockIdx.x * 128;
    int tid = threadIdx.x, lane = tid & 31, wid = tid >> 5;
    int wmL = (wid >> 2) * 64, wnL = (wid & 3) * 32;

    wmma::fragment<wmma::accumulator, 16, 16, 16, float> acc[4][2];
    #pragma unroll
    for (int i = 0; i < 4; i++)
        #pragma unroll
        for (int j = 0; j < 2; j++) wmma::fill_fragment(acc[i][j], 0.0f);

    int ar = tid >> 1, ac = (tid & 1) * 8;
    int br = tid >> 4, bc = (tid & 15) * 8;

    auto copyAB = [&](int kt, int buf) {
        int k0 = kt * 16;
        *(float4*)&sA[buf * 3072 + ar * 24 + ac] =
            *(const float4*)&g_Mh[(size_t)(m0 + ar) * CI + k0 + ac];
        *(float4*)&sB[buf * 2176 + br * 136 + bc] =
            *(const float4*)&g_crossh[(size_t)(k0 + br) * NPJ + n0 + bc];
    };

    copyAB(0, 0);
    __syncthreads();
    for (int kt = 0; kt < 12; kt++) {
        int buf = kt & 1;
        if (kt + 1 < 12) copyAB(kt + 1, buf ^ 1);
        wmma::fragment<wmma::matrix_a, 16, 16, 16, __half, wmma::row_major> af[4];
        wmma::fragment<wmma::matrix_b, 16, 16, 16, __half, wmma::row_major> bf[2];
        #pragma unroll
        for (int i = 0; i < 4; i++)
            wmma::load_matrix_sync(af[i], &sA[buf * 3072 + (wmL + i * 16) * 24], 24);
        #pragma unroll
        for (int j = 0; j < 2; j++)
            wmma::load_matrix_sync(bf[j], &sB[buf * 2176 + wnL + j * 16], 136);
        #pragma unroll
        for (int i = 0; i < 4; i++)
            #pragma unroll
            for (int j = 0; j < 2; j++)
                wmma::mma_sync(acc[i][j], af[i], bf[j], acc[i][j]);
        __syncthreads();
    }

    // --- fused softmax epilogue ---
    float* sCw = sC + wid * 64 * 36;       // per-warp 64x36 tile
    #pragma unroll
    for (int i = 0; i < 4; i++)
        #pragma unroll
        for (int j = 0; j < 2; j++)
            wmma::store_matrix_sync(&sCw[(i * 16) * 36 + j * 16], acc[i][j], 36,
                                    wmma::mem_row_major);
    __syncwarp();
    #pragma unroll
    for (int it = 0; it < 4; it++) {
        int g = lane + it * 32;            // 0..127 groups: 64 rows x 2 halves
        int row = g >> 1, half = g & 1;
        const float* src = &sCw[row * 36 + half * 16];
        float v[16];
        #pragma unroll
        for (int q = 0; q < 16; q++) v[q] = src[q];
        float mx = v[0];
        #pragma unroll
        for (int q = 1; q < 16; q++) mx = fmaxf(mx, v[q]);
        float s = 0.f;
        #pragma unroll
        for (int q = 0; q < 16; q++) { v[q] = __expf(v[q] - mx); s += v[q]; }
        float inv = 1.f / s;
        __align__(16) __half hv[16];
        #pragma unroll
        for (int q = 0; q < 16; q++) hv[q] = __float2half_rn(v[q] * inv);
        size_t off = (size_t)(m0 + wmL + row) * NPJ + n0 + wnL + half * 16;
        *(uint4*)&g_acth[off]     = *(uint4*)&hv[0];
        *(uint4*)&g_acth[off + 8] = *(uint4*)&hv[8];
    }
}

// ------------------------- K4a: nfm[(k,r)][ci][p] (fp16) = sum_j act*cross ------------
// One thread per p. grid (V/128, 12, 8) keyed on (p-tile, k, h). The 12 act rows
// for (h,k) are register-cached as packed f32x2 (2 passes x 6 rows, R11 shape);
// inner dot uses Blackwell fma.rn.f32x2 -> 8 dual-lane FMA + 1 cross-lane add
// per output instead of 16 scalar FFMA.
__global__ __launch_bounds__(128) void k4a_nfm() {
    int k = blockIdx.y;                    // 0..11
    int h = blockIdx.z;                    // 0..7
    int p = blockIdx.x * 128 + threadIdx.x;
    int abase = (h * 12 + k) * 12;
    #pragma unroll
    for (int rp = 0; rp < 2; rp++) {
        unsigned long long av2[6][8];
        #pragma unroll
        for (int rr = 0; rr < 6; rr++) {
            size_t aoff = (size_t)(abase + rp * 6 + rr) * NPJ + p * NB;
            uint4 a0 = *(const uint4*)&g_acth[aoff];
            uint4 a1 = *(const uint4*)&g_acth[aoff + 8];
            const __half2* h0 = (const __half2*)&a0;
            const __half2* h1 = (const __half2*)&a1;
            #pragma unroll
            for (int q = 0; q < 4; q++) {
                av2[rr][q]     = h2_to_f32x2(h0[q]);
                av2[rr][4 + q] = h2_to_f32x2(h1[q]);
            }
        }
        #pragma unroll 4
        for (int cc = 0; cc < 24; cc++) {
            int ci = h * 24 + cc;
            size_t xoff = (size_t)ci * NPJ + p * NB;
            uint4 x0 = *(const uint4*)&g_crossh[xoff];
            uint4 x1 = *(const uint4*)&g_crossh[xoff + 8];
            const __half2* h0 = (const __half2*)&x0;
            const __half2* h1 = (const __half2*)&x1;
            unsigned long long xv2[8];
            #pragma unroll
            for (int q = 0; q < 4; q++) {
                xv2[q]     = h2_to_f32x2(h0[q]);
                xv2[4 + q] = h2_to_f32x2(h1[q]);
            }
            #pragma unroll
            for (int rr = 0; rr < 6; rr++) {
                unsigned long long acc2 = 0ull;   // {0.f, 0.f}
                #pragma unroll
                for (int q = 0; q < 8; q++) acc2 = ffma2(av2[rr][q], xv2[q], acc2);
                float lo, hi;
                asm("mov.b64 {%0, %1}, %2;" : "=f"(lo), "=f"(hi) : "l"(acc2));
                g_nfmh[((size_t)(k * 12 + rp * 6 + rr) * CI + ci) * V + p] =
                    __float2half_rn(lo + hi);
            }
        }
    }
}

// ------------------------- K4b: ka[r] = sum over 13 slabs of W_slab @ B_slab ----------
// Per r: 12 x (Wf(k,r) 64x192 @ nfm(k,r) 192x2048) + Wc(r) @ fmT. Accum fp32 -> g_ka.
// grid (32, 12) = 384 CTAs, 128 threads = 4 warps; block tile 64 x 64, k-step 32,
// 78 double-buffered iterations, 8 MMAs/iter.
__global__ __launch_bounds__(128) void k4b_ka() {
    __shared__ __align__(16) __half sA[2][64][40];   // 64 x 32 (+8 pad)
    __shared__ __align__(16) __half sB[2][32][72];   // 32 x 64 (+8 pad)
    int r = blockIdx.y;
    int n0 = blockIdx.x * 64;
    int tid = threadIdx.x, wid = tid >> 5;
    int wn = wid * 16;

    wmma::fragment<wmma::accumulator, 16, 16, 16, float> acc[4];
    #pragma unroll
    for (int i = 0; i < 4; i++) wmma::fill_fragment(acc[i], 0.0f);

    auto aPtr = [&](int s) -> const __half* {
        return (s < 12) ? g_Wfh + (size_t)(s * 12 + r) * DO * CI
                        : g_Wch + (size_t)r * DO * CI;
    };
    auto bPtr = [&](int s) -> const __half* {
        return (s < 12) ? g_nfmh + (size_t)(s * 12 + r) * CI * V
                        : g_fmTh;
    };

    auto copyAB = [&](int it, int buf) {
        int s = it / 6, k0 = (it % 6) * 32;
        const __half* A = aPtr(s);
        const __half* B = bPtr(s);
        #pragma unroll
        for (int q = 0; q < 2; q++) {      // A: 64x32 = 256 float4, 2/thread
            int f = tid * 2 + q;
            int row = f >> 2, seg = (f & 3) * 8;
            *(float4*)&sA[buf][row][seg] = *(const float4*)&A[(size_t)row * CI + k0 + seg];
        }
        #pragma unroll
        for (int q = 0; q < 2; q++) {      // B: 32x64 = 256 float4, 2/thread
            int f = tid * 2 + q;
            int row = f >> 3, seg = (f & 7) * 8;
            *(float4*)&sB[buf][row][seg] = *(const float4*)&B[(size_t)(k0 + row) * V + n0 + seg];
        }
    };

    const int NIT = 13 * 6;    // 78
    copyAB(0, 0);
    __syncthreads();
    for (int it = 0; it < NIT; it++) {
        int buf = it & 1;
        if (it + 1 < NIT) copyAB(it + 1, buf ^ 1);
        #pragma unroll
        for (int kk = 0; kk < 2; kk++) {
            wmma::fragment<wmma::matrix_a, 16, 16, 16, __half, wmma::row_major> af[4];
            wmma::fragment<wmma::matrix_b, 16, 16, 16, __half, wmma::row_major> bf;
            #pragma unroll
            for (int i = 0; i < 4; i++)
                wmma::load_matrix_sync(af[i], &sA[buf][i * 16][kk * 16], 40);
            wmma::load_matrix_sync(bf, &sB[buf][kk * 16][wn], 72);
            #pragma unroll
            for (int i = 0; i < 4; i++)
                wmma::mma_sync(acc[i], af[i], bf, acc[i]);
        }
        __syncthreads();
    }
    #pragma unroll
    for (int i = 0; i < 4; i++)
        wmma::store_matrix_sync(g_ka + ((size_t)r * DO + i * 16) * V + n0 + wn,
                                acc[i], V, wmma::mem_row_major);
}

// ------------------------- K5: color-pair max + fm copy ----------------
__global__ void k5_final(const float* __restrict__ fm, float* __restrict__ out) {
    int idx = blockIdx.x * blockDim.x + threadIdx.x;
    const int NKA = DO * V;                // 131072
    if (idx < NKA) {
        int d = idx / V, p = idx % V;
        float ka[12];
        #pragma unroll
        for (int r = 0; r < 12; r++) ka[r] = g_ka[(size_t)(r * DO + d) * V + p];
        #pragma unroll
        for (int cc = 0; cc < 6; cc++)
            out[d * (V * 6) + p * 6 + cc] = fmaxf(ka[c_C2V[cc][0]], ka[c_C2V[cc][1]]);
    } else {
        int j = idx - NKA;
        if (j < DI * V * 6)
            out[DO * V * 6 + j] = fm[j];
    }
}

// ------------------------- launch -------------------------
extern "C" void kernel_launch(void* const* d_in, const int* in_sizes, int n_in,
                              void* d_out, int out_size) {
    const int*   nbr   = (const int*)d_in[0];
    const float* verts = (const float*)d_in[1];
    const float* fm    = (const float*)d_in[2];
    const float* Wdim  = (const float*)d_in[3];
    const float* W     = (const float*)d_in[4];
    const float* Wdir  = (const float*)d_in[5];
    float* out = (float*)d_out;

    const int K2_SMEM = 8 * 64 * 36 * 4;   // 73728 B (sC; covers sA+sB too)
    cudaFuncSetAttribute(k2_act, cudaFuncAttributeMaxDynamicSharedMemorySize, K2_SMEM);

    k0_weights<<<512, 256>>>(W, Wdir, fm);
    k1_cross<<<V, 192>>>(nbr, verts, fm, Wdim);
    k2_act<<<dim3(NPJ / 128, ACT_ROWS / 128), 256, K2_SMEM>>>();
    k4a_nfm<<<dim3(V / 128, 12, 8), 128>>>();
    k4b_ka<<<dim3(V / 64, 12), 128>>>();
    k5_final<<<(DO * V + DI * V * 6 + 255) / 256, 256>>>(fm, out);
}